// round 7
// baseline (speedup 1.0000x reference)
#include <cuda_runtime.h>

#define S_TOT 2000
#define A_TOT 1000
#define I_DIM 5
#define H_DIM 32
#define SPLIT 2                       // struct-range splits per atom (grid.y)
#define S_PER_BLK (S_TOT / SPLIT)
#define NTHREADS 256

__device__ __forceinline__ float tanh_fast(float x) {
    asm("tanh.approx.f32 %0, %0;" : "+f"(x));
    return x;
}

__global__ __launch_bounds__(NTHREADS, 2) void mlp_kernel(
    const float* __restrict__ g,   // [S, A, I]
    const float* __restrict__ W1,  // [A, I, H]
    const float* __restrict__ b1,  // [A, H]
    const float* __restrict__ W2,  // [A, H, H]
    const float* __restrict__ b2,  // [A, H]
    const float* __restrict__ W3,  // [A, H, 1]
    const float* __restrict__ b3,  // [A, 1]
    float* __restrict__ out)       // [S, A]
{
    // Scalar weights in smem; all inner-loop addresses warp-uniform ->
    // conflict-free broadcast.
    __shared__ __align__(16) float w1t[H_DIM * I_DIM];   // transposed: [j][i]
    __shared__ __align__(16) float w2s[H_DIM * H_DIM];   // [j][k], float4 rows
    __shared__ __align__(16) float b1s[H_DIM];
    __shared__ __align__(16) float b2s[H_DIM];
    __shared__ __align__(16) float w3s[H_DIM];
    __shared__ float b3s;

    const int a   = blockIdx.x;
    const int tid = threadIdx.x;

    for (int idx = tid; idx < I_DIM * H_DIM; idx += NTHREADS) {
        int i = idx / H_DIM, j = idx % H_DIM;
        w1t[j * I_DIM + i] = W1[a * I_DIM * H_DIM + idx];
    }
    for (int idx = tid; idx < H_DIM * H_DIM; idx += NTHREADS)
        w2s[idx] = W2[a * H_DIM * H_DIM + idx];
    if (tid < H_DIM) {
        b1s[tid] = b1[a * H_DIM + tid];
        b2s[tid] = b2[a * H_DIM + tid];
        w3s[tid] = W3[a * H_DIM + tid];
    }
    if (tid == 0) b3s = b3[a];
    __syncthreads();

    const int s_base = blockIdx.y * S_PER_BLK;

    // CRITICAL: exactly ONE struct in flight per thread. Compiler unrolling +
    // interleaving of this loop multiplies live-register pressure by the
    // unroll factor (~60 regs/struct x 4 -> spill to local -> ~16 GB of DRAM
    // thrash, the entire 2 ms of rounds 4/6).
    #pragma unroll 1
    for (int t = tid; t < S_PER_BLK; t += NTHREADS) {
        const int s = s_base + t;
        const float* gp = g + (size_t)s * (A_TOT * I_DIM) + a * I_DIM;

        float gv[I_DIM];
        #pragma unroll
        for (int i = 0; i < I_DIM; i++) gv[i] = gp[i];

        // Layer-2 accumulators only; layer 1 streamed one hidden unit at a
        // time (h1 never exists as an array) -> ~60 live regs.
        float acc[H_DIM];
        #pragma unroll
        for (int k = 0; k < H_DIM; k++) acc[k] = b2s[k];

        #pragma unroll
        for (int j = 0; j < H_DIM; j++) {
            float a1 = b1s[j];
            #pragma unroll
            for (int i = 0; i < I_DIM; i++)
                a1 = fmaf(gv[i], w1t[j * I_DIM + i], a1);
            const float hj = tanh_fast(a1);

            const float4* row = (const float4*)&w2s[j * H_DIM];
            #pragma unroll
            for (int q = 0; q < H_DIM / 4; q++) {
                const float4 w = row[q];
                acc[4 * q + 0] = fmaf(hj, w.x, acc[4 * q + 0]);
                acc[4 * q + 1] = fmaf(hj, w.y, acc[4 * q + 1]);
                acc[4 * q + 2] = fmaf(hj, w.z, acc[4 * q + 2]);
                acc[4 * q + 3] = fmaf(hj, w.w, acc[4 * q + 3]);
            }
        }

        // ---- layer 3: e = tanh(acc) . W3 + b3 ----
        float e = b3s;
        #pragma unroll
        for (int k = 0; k < H_DIM; k++)
            e = fmaf(tanh_fast(acc[k]), w3s[k], e);

        out[(size_t)s * A_TOT + a] = e;
    }
}

extern "C" void kernel_launch(void* const* d_in, const int* in_sizes, int n_in,
                              void* d_out, int out_size) {
    const float* g  = (const float*)d_in[0];
    const float* W1 = (const float*)d_in[1];
    const float* b1 = (const float*)d_in[2];
    const float* W2 = (const float*)d_in[3];
    const float* b2 = (const float*)d_in[4];
    const float* W3 = (const float*)d_in[5];
    const float* b3 = (const float*)d_in[6];
    float* out = (float*)d_out;

    dim3 grid(A_TOT, SPLIT);
    mlp_kernel<<<grid, NTHREADS>>>(g, W1, b1, W2, b2, W3, b3, out);
}

// round 8
// speedup vs baseline: 10.0395x; 10.0395x over previous
#include <cuda_runtime.h>

#define S_TOT 2000
#define A_TOT 1000
#define I_DIM 5
#define H_DIM 32
#define SPLIT 2                       // struct-range splits per atom (grid.y)
#define S_PER_BLK (S_TOT / SPLIT)
#define NTHREADS 256

__device__ __forceinline__ float tanh_fast(float x) {
    asm("tanh.approx.f32 %0, %0;" : "+f"(x));
    return x;
}

__global__ __launch_bounds__(NTHREADS, 2) void mlp_kernel(
    const float* __restrict__ g,   // [S, A, I]
    const float* __restrict__ W1,  // [A, I, H]
    const float* __restrict__ b1,  // [A, H]
    const float* __restrict__ W2,  // [A, H, H]
    const float* __restrict__ b2,  // [A, H]
    const float* __restrict__ W3,  // [A, H, 1]
    const float* __restrict__ b3,  // [A, 1]
    float* __restrict__ out)       // [S, A]
{
    // Scalar weights in smem; all inner-loop addresses warp-uniform ->
    // conflict-free broadcast.
    __shared__ __align__(16) float w1t[H_DIM * I_DIM];   // transposed: [j][i]
    __shared__ __align__(16) float w2s[H_DIM * H_DIM];   // [j][k], float4 rows
    __shared__ __align__(16) float b1s[H_DIM];
    __shared__ __align__(16) float b2s[H_DIM];
    __shared__ __align__(16) float w3s[H_DIM];
    __shared__ float b3s;

    const int a   = blockIdx.x;
    const int tid = threadIdx.x;

    for (int idx = tid; idx < I_DIM * H_DIM; idx += NTHREADS) {
        int i = idx / H_DIM, j = idx % H_DIM;
        w1t[j * I_DIM + i] = W1[a * I_DIM * H_DIM + idx];
    }
    for (int idx = tid; idx < H_DIM * H_DIM; idx += NTHREADS)
        w2s[idx] = W2[a * H_DIM * H_DIM + idx];
    if (tid < H_DIM) {
        b1s[tid] = b1[a * H_DIM + tid];
        b2s[tid] = b2[a * H_DIM + tid];
        w3s[tid] = W3[a * H_DIM + tid];
    }
    if (tid == 0) b3s = b3[a];
    __syncthreads();

    const int s_base = blockIdx.y * S_PER_BLK;

    #pragma unroll 1
    for (int t = tid; t < S_PER_BLK; t += NTHREADS) {
        const int s = s_base + t;
        const float* gp = g + (size_t)s * (A_TOT * I_DIM) + a * I_DIM;

        float gv[I_DIM];
        #pragma unroll
        for (int i = 0; i < I_DIM; i++) gv[i] = gp[i];

        float acc[H_DIM];
        #pragma unroll
        for (int k = 0; k < H_DIM; k++) acc[k] = b2s[k];

        // CRITICAL: unroll 1. Fully unrolling this loop exposes 32x8
        // independent LDS.128 loads; ptxas batch-hoists them (~128 regs of
        // in-flight W2 values), blows the 128-reg cap, and spills acc[] ->
        // ~16 GB of local-memory DRAM thrash (the entire 2 ms of rounds
        // 4/6/7). One iteration in flight keeps live regs ~90.
        #pragma unroll 1
        for (int j = 0; j < H_DIM; j++) {
            float a1 = b1s[j];
            #pragma unroll
            for (int i = 0; i < I_DIM; i++)
                a1 = fmaf(gv[i], w1t[j * I_DIM + i], a1);
            const float hj = tanh_fast(a1);

            const float4* row = (const float4*)&w2s[j * H_DIM];
            #pragma unroll
            for (int q = 0; q < H_DIM / 4; q++) {
                const float4 w = row[q];
                acc[4 * q + 0] = fmaf(hj, w.x, acc[4 * q + 0]);
                acc[4 * q + 1] = fmaf(hj, w.y, acc[4 * q + 1]);
                acc[4 * q + 2] = fmaf(hj, w.z, acc[4 * q + 2]);
                acc[4 * q + 3] = fmaf(hj, w.w, acc[4 * q + 3]);
            }
        }

        // ---- layer 3: e = tanh(acc) . W3 + b3 ----
        float e = b3s;
        #pragma unroll
        for (int k = 0; k < H_DIM; k++)
            e = fmaf(tanh_fast(acc[k]), w3s[k], e);

        out[(size_t)s * A_TOT + a] = e;
    }
}

extern "C" void kernel_launch(void* const* d_in, const int* in_sizes, int n_in,
                              void* d_out, int out_size) {
    const float* g  = (const float*)d_in[0];
    const float* W1 = (const float*)d_in[1];
    const float* b1 = (const float*)d_in[2];
    const float* W2 = (const float*)d_in[3];
    const float* b2 = (const float*)d_in[4];
    const float* W3 = (const float*)d_in[5];
    const float* b3 = (const float*)d_in[6];
    float* out = (float*)d_out;

    dim3 grid(A_TOT, SPLIT);
    mlp_kernel<<<grid, NTHREADS>>>(g, W1, b1, W2, b2, W3, b3, out);
}